// round 11
// baseline (speedup 1.0000x reference)
#include <cuda_runtime.h>
#include <cstdint>

// OcrEmbedding: out[b,t,:] = sum_{s=0..3, id!=0} table[id[b,t,s], :]
// B=32, T=512, S=4, D=256, V=50000. Output fp32 [B*T, 256].
//
// Hybrid: 148 TMA CTAs (one per SM, streaming 8-stage ring, warp-specialized)
// handle rows [0, 4736); 2912 LDG CTAs run the champion LDG.128 scheme on the
// rest. The TMA queue carries 1KB per request (vs 512B per LDG entry) through
// a separate in-flight budget; the two paths add under the LTS cap.

#define BT        (32 * 512)
#define D4        64
#define ROW_BYTES 1024

#define TMA_CTAS   148
#define RPT        32                 // rows per TMA CTA
#define TMA_ROWS   (TMA_CTAS * RPT)   // 4736
#define STAGES     8                  // ring stages, 1 row (4KB) each

#define LDG_RPC    4
#define THREADS    256

__device__ __forceinline__ uint32_t smem_u32(const void* p) {
    uint32_t a;
    asm("{ .reg .u64 t; cvta.to.shared.u64 t, %1; cvt.u32.u64 %0, t; }"
        : "=r"(a) : "l"(p));
    return a;
}

__device__ __forceinline__ void mbar_wait(uint32_t mbar_a, uint32_t parity) {
    uint32_t done;
    asm volatile(
        "{\n\t.reg .pred p;\n\t"
        "mbarrier.try_wait.parity.acquire.cta.shared::cta.b64 p, [%1], %2;\n\t"
        "selp.b32 %0, 1, 0, p;\n\t}"
        : "=r"(done) : "r"(mbar_a), "r"(parity) : "memory");
    if (!done) {
        asm volatile(
            "{\n\t.reg .pred P1;\n\t"
            "WL_%=:\n\t"
            "mbarrier.try_wait.parity.acquire.cta.shared::cta.b64 P1, [%0], %1, 0x989680;\n\t"
            "@P1 bra.uni WD_%=;\n\t"
            "bra.uni WL_%=;\n\t"
            "WD_%=:\n\t}"
            :: "r"(mbar_a), "r"(parity) : "memory");
    }
}

__global__ __launch_bounds__(THREADS) void ocr_embed_hybrid2_kernel(
    const int* __restrict__ ids,          // [BT*4]
    const float* __restrict__ table,      // [V*256]
    float4* __restrict__ out)             // [BT, D4]
{
    extern __shared__ float4 ring[];      // [STAGES][4][D4] = 32 KB
    __shared__ __align__(8) uint64_t full_mb[STAGES];
    __shared__ __align__(8) uint64_t empty_mb[STAGES];
    __shared__ int idbuf[RPT * 4];        // 128 ids

    const int tid = threadIdx.x;

    if (blockIdx.x >= TMA_CTAS) {
        // ================= LDG path (champion R1 scheme) =================
        const int row0 = TMA_ROWS + (blockIdx.x - TMA_CTAS) * LDG_RPC;
        const int q    = tid & 63;
        const int row  = row0 + (tid >> 6);

        int4 id = __ldg((const int4*)(ids + row * 4));

        float4 acc = make_float4(0.f, 0.f, 0.f, 0.f);
        if (id.x != 0) {
            float4 v = __ldcs((const float4*)(table + (size_t)id.x * 256) + q);
            acc.x += v.x; acc.y += v.y; acc.z += v.z; acc.w += v.w;
        }
        if (id.y != 0) {
            float4 v = __ldcs((const float4*)(table + (size_t)id.y * 256) + q);
            acc.x += v.x; acc.y += v.y; acc.z += v.z; acc.w += v.w;
        }
        if (id.z != 0) {
            float4 v = __ldcs((const float4*)(table + (size_t)id.z * 256) + q);
            acc.x += v.x; acc.y += v.y; acc.z += v.z; acc.w += v.w;
        }
        if (id.w != 0) {
            float4 v = __ldcs((const float4*)(table + (size_t)id.w * 256) + q);
            acc.x += v.x; acc.y += v.y; acc.z += v.z; acc.w += v.w;
        }
        __stcs(&out[(size_t)row * D4 + q], acc);
        return;
    }

    // ================= TMA path (streaming ring) =================
    const int row0 = blockIdx.x * RPT;

    // Prefetch all 128 ids into smem (full parallelism, one shot).
    if (tid < RPT * 4) idbuf[tid] = __ldg(&ids[row0 * 4 + tid]);

    if (tid == 0) {
        #pragma unroll
        for (int s = 0; s < STAGES; s++) {
            uint32_t f = smem_u32(&full_mb[s]);
            uint32_t e = smem_u32(&empty_mb[s]);
            asm volatile("mbarrier.init.shared.b64 [%0], 4;"  :: "r"(f) : "memory");
            asm volatile("mbarrier.init.shared.b64 [%0], 64;" :: "r"(e) : "memory");
        }
    }
    __syncthreads();

    if (tid < 4) {
        // ---- Producer: 4 threads, one 1KB copy per row each ----
        for (int k = 0; k < RPT; k++) {
            const int s = k & (STAGES - 1);
            const uint32_t fmb = smem_u32(&full_mb[s]);
            if (k >= STAGES) {
                // wait for (k/STAGES - 1)-th consumption of this stage
                mbar_wait(smem_u32(&empty_mb[s]), ((k >> 3) + 1) & 1);
            }
            const int id = idbuf[k * 4 + tid];
            const uint32_t tx = (id != 0) ? ROW_BYTES : 0u;
            asm volatile("mbarrier.arrive.expect_tx.shared.b64 _, [%0], %1;"
                         :: "r"(fmb), "r"(tx) : "memory");
            if (id != 0) {
                const float* src = table + (size_t)id * 256;
                uint32_t dst = smem_u32(&ring[(s * 4 + tid) * D4]);
                asm volatile(
                    "cp.async.bulk.shared::cta.global.mbarrier::complete_tx::bytes "
                    "[%0], [%1], %2, [%3];"
                    :: "r"(dst), "l"(src), "n"(ROW_BYTES), "r"(fmb) : "memory");
            }
        }
    } else if (tid >= 64) {
        // ---- Consumers: 3 independent groups of 64 threads ----
        const int cg = (tid >> 6) - 1;    // 0..2
        const int t  = tid & 63;

        for (int k = cg; k < RPT; k += 3) {
            const int s = k & (STAGES - 1);
            mbar_wait(smem_u32(&full_mb[s]), (k >> 3) & 1);

            const int i0 = idbuf[k * 4 + 0];
            const int i1 = idbuf[k * 4 + 1];
            const int i2 = idbuf[k * 4 + 2];
            const int i3 = idbuf[k * 4 + 3];

            const float4* p = &ring[(s * 4) * D4 + t];
            float4 acc = make_float4(0.f, 0.f, 0.f, 0.f);
            if (i0 != 0) { float4 v = p[0];      acc.x += v.x; acc.y += v.y; acc.z += v.z; acc.w += v.w; }
            if (i1 != 0) { float4 v = p[D4];     acc.x += v.x; acc.y += v.y; acc.z += v.z; acc.w += v.w; }
            if (i2 != 0) { float4 v = p[2 * D4]; acc.x += v.x; acc.y += v.y; acc.z += v.z; acc.w += v.w; }
            if (i3 != 0) { float4 v = p[3 * D4]; acc.x += v.x; acc.y += v.y; acc.z += v.z; acc.w += v.w; }

            __stcs(&out[(size_t)(row0 + k) * D4 + t], acc);

            asm volatile("mbarrier.arrive.shared.b64 _, [%0];"
                         :: "r"(smem_u32(&empty_mb[s])) : "memory");
        }
    }
    // threads 4..63 have no pipeline role and simply exit.
}

extern "C" void kernel_launch(void* const* d_in, const int* in_sizes, int n_in,
                              void* d_out, int out_size)
{
    const int*   ids   = (const int*)d_in[0];
    const float* table = (const float*)d_in[1];
    float4*      out   = (float4*)d_out;

    const int smem = STAGES * 4 * D4 * sizeof(float4);   // 32 KB

    static bool attr_set = false;
    if (!attr_set) {
        cudaFuncSetAttribute(ocr_embed_hybrid2_kernel,
                             cudaFuncAttributeMaxDynamicSharedMemorySize, smem);
        attr_set = true;
    }

    const int ldg_ctas = (BT - TMA_ROWS) / LDG_RPC;  // 2912
    const int blocks   = TMA_CTAS + ldg_ctas;        // 3060

    ocr_embed_hybrid2_kernel<<<blocks, THREADS, smem>>>(ids, table, out);
}

// round 12
// speedup vs baseline: 1.4132x; 1.4132x over previous
#include <cuda_runtime.h>
#include <cstdint>

// OcrEmbedding: out[b,t,:] = sum_{s=0..3, id!=0} table[id[b,t,s], :]
// B=32, T=512, S=4, D=256, V=50000.
// d_in[0] = subtoken_ids (int32, B*T*S), d_in[1] = table (float32, V*D)
// Output: float32, B*T*D.
//
// 256-bit gather experiment (sm_100+ LDG.E.256): evidence from rounds 1-11
// says gather throughput ~ (outstanding LDG entries/SM) x (bytes/entry):
// LDG.32 -> 1.8 TB/s, LDG.128 -> 7.9 TB/s. ld.global.nc.v8.f32 doubles
// bytes/entry again: one warp-level LDG.256 = 1024B = one full table row.
// Layout: one warp per token row, each lane owns an aligned 32B chunk.

#define BT (32 * 512)    // 16384 token rows

struct F8 { float v[8]; };

__device__ __forceinline__ F8 ldg256(const float* p) {
    F8 r;
    asm volatile("ld.global.nc.v8.f32 {%0,%1,%2,%3,%4,%5,%6,%7}, [%8];"
                 : "=f"(r.v[0]), "=f"(r.v[1]), "=f"(r.v[2]), "=f"(r.v[3]),
                   "=f"(r.v[4]), "=f"(r.v[5]), "=f"(r.v[6]), "=f"(r.v[7])
                 : "l"(p));
    return r;
}

__device__ __forceinline__ void stg256(float* p, const F8& r) {
    asm volatile("st.global.v8.f32 [%0], {%1,%2,%3,%4,%5,%6,%7,%8};"
                 :: "l"(p),
                    "f"(r.v[0]), "f"(r.v[1]), "f"(r.v[2]), "f"(r.v[3]),
                    "f"(r.v[4]), "f"(r.v[5]), "f"(r.v[6]), "f"(r.v[7])
                 : "memory");
}

__global__ __launch_bounds__(256) void ocr_embed_v8_kernel(
    const int* __restrict__ ids,          // [BT*4]
    const float* __restrict__ table,      // [V*256]
    float* __restrict__ out)              // [BT*256]
{
    const int gid  = blockIdx.x * 256 + threadIdx.x;
    const int row  = gid >> 5;            // one warp per token row
    const int lane = gid & 31;            // 32B chunk: floats [lane*8, lane*8+8)
    const int off  = lane * 8;

    const int4 id = __ldg((const int4*)(ids + row * 4));  // warp-broadcast

    F8 s;
    #pragma unroll
    for (int i = 0; i < 8; i++) s.v[i] = 0.f;

    if (id.x != 0) {
        F8 a = ldg256(table + (size_t)id.x * 256 + off);
        #pragma unroll
        for (int i = 0; i < 8; i++) s.v[i] += a.v[i];
    }
    if (id.y != 0) {
        F8 a = ldg256(table + (size_t)id.y * 256 + off);
        #pragma unroll
        for (int i = 0; i < 8; i++) s.v[i] += a.v[i];
    }
    if (id.z != 0) {
        F8 a = ldg256(table + (size_t)id.z * 256 + off);
        #pragma unroll
        for (int i = 0; i < 8; i++) s.v[i] += a.v[i];
    }
    if (id.w != 0) {
        F8 a = ldg256(table + (size_t)id.w * 256 + off);
        #pragma unroll
        for (int i = 0; i < 8; i++) s.v[i] += a.v[i];
    }

    stg256(out + (size_t)row * 256 + off, s);
}

extern "C" void kernel_launch(void* const* d_in, const int* in_sizes, int n_in,
                              void* d_out, int out_size)
{
    const int*   ids   = (const int*)d_in[0];
    const float* table = (const float*)d_in[1];
    float*       out   = (float*)d_out;

    const int total   = BT * 32;          // one warp per row
    const int threads = 256;
    const int blocks  = total / threads;  // 2048

    ocr_embed_v8_kernel<<<blocks, threads>>>(ids, table, out);
}